// round 11
// baseline (speedup 1.0000x reference)
#include <cuda_runtime.h>
#include <cstdint>

#define NWARPS 4           // warps per block
#define PAIRS  8           // token pairs per warp tile
#define TOKPT  16          // tokens per warp tile
#define DIMK   32
#define NHEAD  4
#define NMAT   5           // Wv + 4*Wk
#define KT_STRIDE 33       // keyT row stride (scalar conflict-free)
#define QT_STRIDE 36       // qT row stride (16B-aligned, LDS.128 conflict-free)

struct __align__(16) Smem {
    float4 w4a[DIMK / 2][DIMK];           //  8192 B  (Wv, Wk0) paired per (d2,k)
    float4 w4b[DIMK / 2][DIMK];           //  8192 B  (Wk1, Wk2)
    float2 w2c[DIMK / 2][DIMK];           //  4096 B  Wk3
    float  qT[NWARPS][64 * QT_STRIDE];    // 36864 B
    float  keyT[NWARPS][32 * KT_STRIDE];  // 16896 B (also emb stage)
    float  g12p[NHEAD][36];               //   576 B (float4-readable rows)
    float  gate[NWARPS][64];              //  1024 B
};                                        // total 75840 B -> 3 CTAs/SM

__device__ __forceinline__ uint32_t smem_u32(const void* p) {
    uint32_t a; asm("{.reg .u64 t; cvta.to.shared.u64 t, %1; cvt.u32.u64 %0, t;}" : "=r"(a) : "l"(p));
    return a;
}
__device__ __forceinline__ void cp_async16(uint32_t dst, const void* src) {
    asm volatile("cp.async.cg.shared.global [%0], [%1], 16;" :: "r"(dst), "l"(src) : "memory");
}
#define CP_COMMIT() asm volatile("cp.async.commit_group;" ::: "memory")
#define CP_WAIT0()  asm volatile("cp.async.wait_group 0;" ::: "memory")

__device__ __forceinline__ uint64_t pack2(float lo, float hi) {
    uint64_t r; asm("mov.b64 %0,{%1,%2};" : "=l"(r) : "f"(lo), "f"(hi)); return r;
}
__device__ __forceinline__ void unpack2(uint64_t v, float& a, float& b) {
    asm("mov.b64 {%0,%1},%2;" : "=f"(a), "=f"(b) : "l"(v));
}
__device__ __forceinline__ uint64_t ffma2(uint64_t a, uint64_t b, uint64_t c) {
    uint64_t d; asm("fma.rn.f32x2 %0,%1,%2,%3;" : "=l"(d) : "l"(a), "l"(b), "l"(c)); return d;
}
__device__ __forceinline__ uint64_t fmul2(uint64_t a, uint64_t b) {
    uint64_t d; asm("mul.rn.f32x2 %0,%1,%2;" : "=l"(d) : "l"(a), "l"(b)); return d;
}
__device__ __forceinline__ float rsqrt_a(float x){ float r; asm("rsqrt.approx.f32 %0,%1;" : "=f"(r) : "f"(x)); return r; }
__device__ __forceinline__ float sqrt_a (float x){ float r; asm("sqrt.approx.f32 %0,%1;"  : "=f"(r) : "f"(x)); return r; }
__device__ __forceinline__ float ex2_a  (float x){ float r; asm("ex2.approx.f32 %0,%1;"   : "=f"(r) : "f"(x)); return r; }
__device__ __forceinline__ float rcp_a  (float x){ float r; asm("rcp.approx.f32 %0,%1;"   : "=f"(r) : "f"(x)); return r; }

__global__ void __launch_bounds__(NWARPS * 32, 3)
engram_kernel(const float* __restrict__ emb,
              const float* __restrict__ hid,
              const float* __restrict__ Wv,
              const float* __restrict__ bv,
              const float* __restrict__ Wk,
              const float* __restrict__ bk,
              const float* __restrict__ g1,
              const float* __restrict__ g2,
              float* __restrict__ out,
              int ntiles)
{
    extern __shared__ char smem_raw[];
    Smem& s = *reinterpret_cast<Smem*>(smem_raw);

    const int tid  = threadIdx.x;
    const int lane = tid & 31;
    const int warp = tid >> 5;

    // ---- one-time setup: paired weight layout ----
    for (int i = tid; i < (DIMK / 2) * DIMK; i += blockDim.x) {
        int d2 = i / DIMK, k = i % DIMK;
        int r0 = k * DIMK + 2 * d2, r1 = r0 + 1;
        s.w4a[d2][k] = make_float4(Wv[r0], Wv[r1], Wk[r0], Wk[r1]);
        s.w4b[d2][k] = make_float4(Wk[1024 + r0], Wk[1024 + r1],
                                   Wk[2048 + r0], Wk[2048 + r1]);
        s.w2c[d2][k] = make_float2(Wk[3072 + r0], Wk[3072 + r1]);
    }
    for (int i = tid; i < NHEAD * DIMK; i += blockDim.x)
        s.g12p[i / DIMK][i % DIMK] = g1[i] * g2[i];

    // ---- bias in registers (per-lane column) ----
    float bias_r[NMAT];
    bias_r[0] = bv[lane];
#pragma unroll
    for (int m = 1; m < NMAT; ++m) bias_r[m] = bk[(m - 1) * DIMK + lane];
    __syncthreads();

    const float EPSF  = 1.1920929e-07f;
    const float INV32 = 0.03125f;
    const float ISQ32 = 0.17677669529663687f;   // 1/sqrt(32)
    const float LOG2E = 1.4426950408889634f;

    float*  kt   = s.keyT[warp];
    float*  qt   = s.qT[warp];
    const uint32_t qt_u32 = smem_u32(qt);
    float2* embs = reinterpret_cast<float2*>(kt);           // stage view (GEMV phase)
    const float4* emb4 = reinterpret_cast<const float4*>(kt);

    const int o  = lane >> 3;   // q staging: head of this lane's 16B chunk
    const int l8 = lane & 7;

    for (int tile = blockIdx.x * NWARPS + warp; tile < ntiles;
         tile += gridDim.x * NWARPS) {

        const int base = tile * TOKPT;

        // ---- stage emb pairs into keyT region ----
        const float* embp = emb + (size_t)base * DIMK;
#pragma unroll
        for (int p = 0; p < PAIRS; ++p) {
            float e0 = embp[(2 * p) * DIMK + lane];
            float e1 = embp[(2 * p + 1) * DIMK + lane];
            embs[p * DIMK + lane] = make_float2(e0, e1);
        }

        // ---- q for BOTH rounds via cp.async (latency covered by GEMV) ----
        {
            const float* src0 = hid + ((size_t)base * 128 + (size_t)lane * 4);
#pragma unroll
            for (int t = 0; t < TOKPT; ++t) {
                uint32_t dst = qt_u32 + (((4 * t + o) * QT_STRIDE + 4 * l8) << 2);
                cp_async16(dst, src0 + (size_t)t * 128);
            }
            CP_COMMIT();
        }
        __syncwarp();

        // ---- accumulators: acc[mat][pair] packs 2 tokens, lane = k ----
        uint64_t acc[NMAT][PAIRS];
#pragma unroll
        for (int m = 0; m < NMAT; ++m) {
            uint64_t b2 = pack2(bias_r[m], bias_r[m]);
#pragma unroll
            for (int p = 0; p < PAIRS; ++p) acc[m][p] = b2;
        }

        // ---- GEMV: paired weight loads ----
#pragma unroll 4
        for (int d2 = 0; d2 < DIMK / 2; ++d2) {
            float4 wA = s.w4a[d2][lane];     // (Wv_d0, Wv_d1, Wk0_d0, Wk0_d1)
            float4 wB = s.w4b[d2][lane];     // (Wk1_d0, Wk1_d1, Wk2_d0, Wk2_d1)
            float2 wC = s.w2c[d2][lane];     // (Wk3_d0, Wk3_d1)
            uint64_t wa[NMAT], wb[NMAT];
            wa[0] = pack2(wA.x, wA.x); wb[0] = pack2(wA.y, wA.y);
            wa[1] = pack2(wA.z, wA.z); wb[1] = pack2(wA.w, wA.w);
            wa[2] = pack2(wB.x, wB.x); wb[2] = pack2(wB.y, wB.y);
            wa[3] = pack2(wB.z, wB.z); wb[3] = pack2(wB.w, wB.w);
            wa[4] = pack2(wC.x, wC.x); wb[4] = pack2(wC.y, wC.y);
#pragma unroll
            for (int p = 0; p < PAIRS; ++p) {
                float4 e = emb4[p * (DIMK / 2) + d2];
                uint64_t ea = pack2(e.x, e.y);
                uint64_t eb = pack2(e.z, e.w);
#pragma unroll
                for (int m = 0; m < NMAT; ++m) {
                    acc[m][p] = ffma2(ea, wa[m], acc[m][p]);
                    acc[m][p] = ffma2(eb, wb[m], acc[m][p]);
                }
            }
        }
        CP_WAIT0();       // q ready (was issued ~GEMV-duration ago)
        __syncwarp();     // emb stage dead; keyT region free; qT visible warp-wide

        // ---- 2 rounds: per-round key transpose (32 rows) + combo ----
#pragma unroll
        for (int r = 0; r < 2; ++r) {
#pragma unroll
            for (int h = 0; h < NHEAD; ++h)
#pragma unroll
                for (int pl = 0; pl < 4; ++pl) {
                    float lo, hi; unpack2(acc[1 + h][4 * r + pl], lo, hi);
                    kt[(8 * pl + h)     * KT_STRIDE + lane] = lo;   // t_local = 2*pl
                    kt[(8 * pl + 4 + h) * KT_STRIDE + lane] = hi;   // t_local = 2*pl+1
                }
            __syncwarp();

            // lane owns combo: h = lane&3, t = 8r + (lane>>2)
            const int h = lane & 3;
            const float*  keyrow = kt + lane * KT_STRIDE;
            const float4* qrow4  = reinterpret_cast<const float4*>(
                qt + (32 * r + lane) * QT_STRIDE);
            const float4* grow4  = reinterpret_cast<const float4*>(s.g12p[h]);

            float kss = 0.f, qss = 0.f, pdot = 0.f;
#pragma unroll
            for (int kk = 0; kk < 8; ++kk) {
                float4 q4 = qrow4[kk];                     // LDS.128 conflict-free
                float4 g4 = grow4[kk];                     // LDS.128 merged broadcast
                float k0 = keyrow[4 * kk + 0];
                float k1 = keyrow[4 * kk + 1];
                float k2 = keyrow[4 * kk + 2];
                float k3 = keyrow[4 * kk + 3];
                kss  = fmaf(k0, k0, kss); qss = fmaf(q4.x, q4.x, qss);
                pdot = fmaf(k0 * q4.x, g4.x, pdot);
                kss  = fmaf(k1, k1, kss); qss = fmaf(q4.y, q4.y, qss);
                pdot = fmaf(k1 * q4.y, g4.y, pdot);
                kss  = fmaf(k2, k2, kss); qss = fmaf(q4.z, q4.z, qss);
                pdot = fmaf(k2 * q4.z, g4.z, pdot);
                kss  = fmaf(k3, k3, kss); qss = fmaf(q4.w, q4.w, qss);
                pdot = fmaf(k3 * q4.w, g4.w, pdot);
            }

            float rk = rsqrt_a(fmaf(kss, INV32, EPSF));
            float rq = rsqrt_a(fmaf(qss, INV32, EPSF));
            float gp = pdot * rk * rq * ISQ32;
            float a  = fmaxf(fabsf(gp), 1e-6f);
            float sr = copysignf(sqrt_a(a), gp);
            float ex = ex2_a(-sr * LOG2E);
            s.gate[warp][h * 16 + 8 * r + (lane >> 2)] = rcp_a(1.f + ex);
            __syncwarp();   // keyT reused next round / gates ready
        }

        // ---- output: out[tok][h][k] = gate * value ----
        float* outp = out + (size_t)base * (NHEAD * DIMK);
#pragma unroll
        for (int p = 0; p < PAIRS; ++p) {
#pragma unroll
            for (int h = 0; h < NHEAD; ++h) {
                uint64_t g2v = *reinterpret_cast<const uint64_t*>(
                    &s.gate[warp][h * 16 + 2 * p]);
                uint64_t ov = fmul2(g2v, acc[0][p]);
                float o0, o1; unpack2(ov, o0, o1);
                outp[(2 * p)     * (NHEAD * DIMK) + h * DIMK + lane] = o0;
                outp[(2 * p + 1) * (NHEAD * DIMK) + h * DIMK + lane] = o1;
            }
        }
        __syncwarp();   // protect gate/keyT/qT before next tile
    }
}

extern "C" void kernel_launch(void* const* d_in, const int* in_sizes, int n_in,
                              void* d_out, int out_size)
{
    const float* emb = (const float*)d_in[0];
    const float* hid = (const float*)d_in[1];
    const float* Wv  = (const float*)d_in[2];
    const float* bv  = (const float*)d_in[3];
    const float* Wk  = (const float*)d_in[4];
    const float* bk  = (const float*)d_in[5];
    const float* g1  = (const float*)d_in[6];
    const float* g2  = (const float*)d_in[7];

    int ntok   = in_sizes[0] / DIMK;   // B*S
    int ntiles = ntok / TOKPT;         // 16384 for this shape

    size_t smem = sizeof(Smem);
    cudaFuncSetAttribute(engram_kernel,
                         cudaFuncAttributeMaxDynamicSharedMemorySize, (int)smem);

    int blocks = 2048;                 // 8192 warps -> 2 tiles per warp
    engram_kernel<<<blocks, NWARPS * 32, smem>>>(
        emb, hid, Wv, bv, Wk, bk, g1, g2, (float*)d_out, ntiles);
}

// round 12
// speedup vs baseline: 1.0077x; 1.0077x over previous
#include <cuda_runtime.h>
#include <cstdint>

#define NWARPS 4           // warps per block
#define PAIRS  8           // token pairs per warp tile
#define TOKPT  16          // tokens per warp tile
#define DIMK   32
#define NHEAD  4
#define NMAT   5           // Wv + 4*Wk
#define KT_STRIDE 33       // keyT row stride (scalar conflict-free)
#define QT_STRIDE 36       // qT row stride (16B-aligned, LDS.128 conflict-free)

struct __align__(16) Smem {
    float2 w2[NMAT][DIMK / 2][DIMK];      // 20480 B
    float  qT[NWARPS][64 * QT_STRIDE];    // 36864 B
    float  keyT[NWARPS][32 * KT_STRIDE];  // 16896 B (also emb stage)
    float  bias[NMAT][DIMK];              //   640 B
    float  g12p[NHEAD][KT_STRIDE];        //   528 B
    float  gate[NWARPS][64];              //  1024 B
};                                        // total 76432 B -> 3 CTAs/SM

__device__ __forceinline__ uint32_t smem_u32(const void* p) {
    uint32_t a; asm("{.reg .u64 t; cvta.to.shared.u64 t, %1; cvt.u32.u64 %0, t;}" : "=r"(a) : "l"(p));
    return a;
}
__device__ __forceinline__ void cp_async16(uint32_t dst, const void* src) {
    asm volatile("cp.async.cg.shared.global [%0], [%1], 16;" :: "r"(dst), "l"(src) : "memory");
}
#define CP_COMMIT() asm volatile("cp.async.commit_group;" ::: "memory")
#define CP_WAIT0()  asm volatile("cp.async.wait_group 0;" ::: "memory")

__device__ __forceinline__ uint64_t pack2(float lo, float hi) {
    uint64_t r; asm("mov.b64 %0,{%1,%2};" : "=l"(r) : "f"(lo), "f"(hi)); return r;
}
__device__ __forceinline__ void unpack2(uint64_t v, float& a, float& b) {
    asm("mov.b64 {%0,%1},%2;" : "=f"(a), "=f"(b) : "l"(v));
}
__device__ __forceinline__ uint64_t ffma2(uint64_t a, uint64_t b, uint64_t c) {
    uint64_t d; asm("fma.rn.f32x2 %0,%1,%2,%3;" : "=l"(d) : "l"(a), "l"(b), "l"(c)); return d;
}
__device__ __forceinline__ uint64_t fmul2(uint64_t a, uint64_t b) {
    uint64_t d; asm("mul.rn.f32x2 %0,%1,%2;" : "=l"(d) : "l"(a), "l"(b)); return d;
}
__device__ __forceinline__ float rsqrt_a(float x){ float r; asm("rsqrt.approx.f32 %0,%1;" : "=f"(r) : "f"(x)); return r; }
__device__ __forceinline__ float sqrt_a (float x){ float r; asm("sqrt.approx.f32 %0,%1;"  : "=f"(r) : "f"(x)); return r; }
__device__ __forceinline__ float ex2_a  (float x){ float r; asm("ex2.approx.f32 %0,%1;"   : "=f"(r) : "f"(x)); return r; }
__device__ __forceinline__ float rcp_a  (float x){ float r; asm("rcp.approx.f32 %0,%1;"   : "=f"(r) : "f"(x)); return r; }

__global__ void __launch_bounds__(NWARPS * 32, 3)
engram_kernel(const float* __restrict__ emb,
              const float* __restrict__ hid,
              const float* __restrict__ Wv,
              const float* __restrict__ bv,
              const float* __restrict__ Wk,
              const float* __restrict__ bk,
              const float* __restrict__ g1,
              const float* __restrict__ g2,
              float* __restrict__ out,
              int ntiles)
{
    extern __shared__ char smem_raw[];
    Smem& s = *reinterpret_cast<Smem*>(smem_raw);

    const int tid  = threadIdx.x;
    const int lane = tid & 31;
    const int warp = tid >> 5;

    // ---- one-time setup ----
    for (int i = tid; i < NMAT * (DIMK / 2) * DIMK; i += blockDim.x) {
        int m   = i / ((DIMK / 2) * DIMK);
        int rem = i % ((DIMK / 2) * DIMK);
        int d2  = rem / DIMK;
        int k   = rem % DIMK;
        const float* W = (m == 0) ? Wv : (Wk + (size_t)(m - 1) * DIMK * DIMK);
        s.w2[m][d2][k] = make_float2(W[k * DIMK + 2 * d2], W[k * DIMK + 2 * d2 + 1]);
    }
    if (tid < DIMK) s.bias[0][tid] = bv[tid];
    for (int i = tid; i < NHEAD * DIMK; i += blockDim.x) {
        s.bias[1 + i / DIMK][i % DIMK] = bk[i];
        s.g12p[i / DIMK][i % DIMK] = g1[i] * g2[i];
    }
    __syncthreads();

    const float EPSF  = 1.1920929e-07f;
    const float INV32 = 0.03125f;
    const float ISQ32 = 0.17677669529663687f;   // 1/sqrt(32)
    const float LOG2E = 1.4426950408889634f;

    float*  kt   = s.keyT[warp];
    float*  qt   = s.qT[warp];
    const uint32_t qt_u32 = smem_u32(qt);
    float2* embs = reinterpret_cast<float2*>(kt);           // stage view (GEMV phase)
    const float4* emb4 = reinterpret_cast<const float4*>(kt);

    const int o  = lane >> 3;   // q staging: head of this lane's 16B chunk
    const int l8 = lane & 7;
    const int stride = gridDim.x * NWARPS;

    // ---- prefetch emb for the FIRST tile into registers ----
    int tile = blockIdx.x * NWARPS + warp;
    float2 epf[PAIRS];
    if (tile < ntiles) {
        const float* embp = emb + (size_t)tile * TOKPT * DIMK;
#pragma unroll
        for (int p = 0; p < PAIRS; ++p) {
            epf[p].x = embp[(2 * p) * DIMK + lane];
            epf[p].y = embp[(2 * p + 1) * DIMK + lane];
        }
    }

    for (; tile < ntiles; tile += stride) {

        const int base = tile * TOKPT;

        // ---- stage prefetched emb pairs into keyT region (STS only) ----
#pragma unroll
        for (int p = 0; p < PAIRS; ++p)
            embs[p * DIMK + lane] = epf[p];

        // ---- q for BOTH rounds via cp.async (latency covered by GEMV) ----
        {
            const float* src0 = hid + ((size_t)base * 128 + (size_t)lane * 4);
#pragma unroll
            for (int t = 0; t < TOKPT; ++t) {
                uint32_t dst = qt_u32 + (((4 * t + o) * QT_STRIDE + 4 * l8) << 2);
                cp_async16(dst, src0 + (size_t)t * 128);
            }
            CP_COMMIT();
        }
        __syncwarp();

        // ---- accumulators: acc[mat][pair] packs 2 tokens, lane = k ----
        uint64_t acc[NMAT][PAIRS];
#pragma unroll
        for (int m = 0; m < NMAT; ++m) {
            float b = s.bias[m][lane];
            uint64_t b2 = pack2(b, b);
#pragma unroll
            for (int p = 0; p < PAIRS; ++p) acc[m][p] = b2;
        }

        // ---- GEMV ----
#pragma unroll 4
        for (int d2 = 0; d2 < DIMK / 2; ++d2) {
            uint64_t wa[NMAT], wb[NMAT];
#pragma unroll
            for (int m = 0; m < NMAT; ++m) {
                float2 w = s.w2[m][d2][lane];
                wa[m] = pack2(w.x, w.x);
                wb[m] = pack2(w.y, w.y);
            }
#pragma unroll
            for (int p = 0; p < PAIRS; ++p) {
                float4 e = emb4[p * (DIMK / 2) + d2];
                uint64_t ea = pack2(e.x, e.y);
                uint64_t eb = pack2(e.z, e.w);
#pragma unroll
                for (int m = 0; m < NMAT; ++m) {
                    acc[m][p] = ffma2(ea, wa[m], acc[m][p]);
                    acc[m][p] = ffma2(eb, wb[m], acc[m][p]);
                }
            }
        }
        CP_WAIT0();       // q ready (was issued ~GEMV-duration ago)
        __syncwarp();     // emb stage dead; keyT region free; qT visible warp-wide

        // ---- prefetch NEXT tile's emb (LDG latency hidden by combo+output) ----
        {
            int nt = tile + stride;
            if (nt < ntiles) {
                const float* embp = emb + (size_t)nt * TOKPT * DIMK;
#pragma unroll
                for (int p = 0; p < PAIRS; ++p) {
                    epf[p].x = embp[(2 * p) * DIMK + lane];
                    epf[p].y = embp[(2 * p + 1) * DIMK + lane];
                }
            }
        }

        // ---- 2 rounds: per-round key transpose (32 rows) + combo ----
#pragma unroll
        for (int r = 0; r < 2; ++r) {
#pragma unroll
            for (int h = 0; h < NHEAD; ++h)
#pragma unroll
                for (int pl = 0; pl < 4; ++pl) {
                    float lo, hi; unpack2(acc[1 + h][4 * r + pl], lo, hi);
                    kt[(8 * pl + h)     * KT_STRIDE + lane] = lo;   // t_local = 2*pl
                    kt[(8 * pl + 4 + h) * KT_STRIDE + lane] = hi;   // t_local = 2*pl+1
                }
            __syncwarp();

            // lane owns combo: h = lane&3, t = 8r + (lane>>2)
            const int h = lane & 3;
            const float*  keyrow = kt + lane * KT_STRIDE;
            const float4* qrow4  = reinterpret_cast<const float4*>(
                qt + (32 * r + lane) * QT_STRIDE);
            const float*  grow   = s.g12p[h];

            float kss = 0.f, qss = 0.f, pdot = 0.f;
#pragma unroll
            for (int kk = 0; kk < 8; ++kk) {
                float4 q4 = qrow4[kk];                     // LDS.128 conflict-free
                float k0 = keyrow[4 * kk + 0];
                float k1 = keyrow[4 * kk + 1];
                float k2 = keyrow[4 * kk + 2];
                float k3 = keyrow[4 * kk + 3];
                float g0 = grow[4 * kk + 0];
                float g1v = grow[4 * kk + 1];
                float g2v = grow[4 * kk + 2];
                float g3 = grow[4 * kk + 3];
                kss  = fmaf(k0, k0, kss); qss = fmaf(q4.x, q4.x, qss);
                pdot = fmaf(k0 * q4.x, g0, pdot);
                kss  = fmaf(k1, k1, kss); qss = fmaf(q4.y, q4.y, qss);
                pdot = fmaf(k1 * q4.y, g1v, pdot);
                kss  = fmaf(k2, k2, kss); qss = fmaf(q4.z, q4.z, qss);
                pdot = fmaf(k2 * q4.z, g2v, pdot);
                kss  = fmaf(k3, k3, kss); qss = fmaf(q4.w, q4.w, qss);
                pdot = fmaf(k3 * q4.w, g3, pdot);
            }

            float rk = rsqrt_a(fmaf(kss, INV32, EPSF));
            float rq = rsqrt_a(fmaf(qss, INV32, EPSF));
            float gp = pdot * rk * rq * ISQ32;
            float a  = fmaxf(fabsf(gp), 1e-6f);
            float sr = copysignf(sqrt_a(a), gp);
            float ex = ex2_a(-sr * LOG2E);
            s.gate[warp][h * 16 + 8 * r + (lane >> 2)] = rcp_a(1.f + ex);
            __syncwarp();   // keyT reused next round / gates ready
        }

        // ---- output: out[tok][h][k] = gate * value ----
        float* outp = out + (size_t)base * (NHEAD * DIMK);
#pragma unroll
        for (int p = 0; p < PAIRS; ++p) {
#pragma unroll
            for (int h = 0; h < NHEAD; ++h) {
                uint64_t g2v = *reinterpret_cast<const uint64_t*>(
                    &s.gate[warp][h * 16 + 2 * p]);
                uint64_t ov = fmul2(g2v, acc[0][p]);
                float o0, o1; unpack2(ov, o0, o1);
                outp[(2 * p)     * (NHEAD * DIMK) + h * DIMK + lane] = o0;
                outp[(2 * p + 1) * (NHEAD * DIMK) + h * DIMK + lane] = o1;
            }
        }
        __syncwarp();   // protect gate/keyT/qT before next tile
    }
}

extern "C" void kernel_launch(void* const* d_in, const int* in_sizes, int n_in,
                              void* d_out, int out_size)
{
    const float* emb = (const float*)d_in[0];
    const float* hid = (const float*)d_in[1];
    const float* Wv  = (const float*)d_in[2];
    const float* bv  = (const float*)d_in[3];
    const float* Wk  = (const float*)d_in[4];
    const float* bk  = (const float*)d_in[5];
    const float* g1  = (const float*)d_in[6];
    const float* g2  = (const float*)d_in[7];

    int ntok   = in_sizes[0] / DIMK;   // B*S
    int ntiles = ntok / TOKPT;         // 16384 for this shape

    size_t smem = sizeof(Smem);
    cudaFuncSetAttribute(engram_kernel,
                         cudaFuncAttributeMaxDynamicSharedMemorySize, (int)smem);

    int blocks = 2048;                 // 8192 warps -> 2 tiles per warp
    engram_kernel<<<blocks, NWARPS * 32, smem>>>(
        emb, hid, Wv, bv, Wk, bk, g1, g2, (float*)d_out, ntiles);
}

// round 13
// speedup vs baseline: 1.1301x; 1.1215x over previous
#include <cuda_runtime.h>
#include <cstdint>

#define NWARPS  4
#define TOKPT   16
#define NTILES_VAL 4      // n-tiles 0..3  = value (Wv)
#define NTILES_ALL 20     // + 16 key n-tiles (4 heads x 4 kgroups)

struct __align__(16) Smem {
    float  Bsm[32][168];         // 21504 B  tf32 bits, [d][n], n = m*32+k (Wv,Wk0..3)
    float  bias[160];            //   640 B  bv | bk
    float  g12p[4][36];          //   576 B  g1*g2, padded rows
    float  qT[NWARPS][16 * 132]; // 33792 B  [t][128] stride 132 (16B-aligned rows)
    float  valT[NWARPS][16 * 36];//  9216 B  value rows, stride 36 (union: A-stage)
    float4 sums[NWARPS][64];     //  4096 B  idx = h*16+t : (kss,qss,pdot,-)
    float  gate[NWARPS][64];     //  1024 B
};                               // total 70848 B -> 3 CTAs/SM

__device__ __forceinline__ uint32_t smem_u32(const void* p) {
    uint32_t a; asm("{.reg .u64 t; cvta.to.shared.u64 t, %1; cvt.u32.u64 %0, t;}" : "=r"(a) : "l"(p));
    return a;
}
__device__ __forceinline__ void cp_async16(uint32_t dst, const void* src) {
    asm volatile("cp.async.cg.shared.global [%0], [%1], 16;" :: "r"(dst), "l"(src) : "memory");
}
#define CP_COMMIT() asm volatile("cp.async.commit_group;" ::: "memory")
#define CP_WAIT1()  asm volatile("cp.async.wait_group 1;" ::: "memory")
#define CP_WAIT0()  asm volatile("cp.async.wait_group 0;" ::: "memory")

__device__ __forceinline__ uint32_t tf32_rna(float x) {
    uint32_t r; asm("cvt.rna.tf32.f32 %0, %1;" : "=r"(r) : "f"(x)); return r;
}
__device__ __forceinline__ void mma_tf32(float& c0, float& c1, float& c2, float& c3,
                                         uint32_t a0, uint32_t a1, uint32_t a2, uint32_t a3,
                                         uint32_t b0, uint32_t b1) {
    asm volatile(
        "mma.sync.aligned.m16n8k8.row.col.f32.tf32.tf32.f32 "
        "{%0,%1,%2,%3}, {%4,%5,%6,%7}, {%8,%9}, {%0,%1,%2,%3};"
        : "+f"(c0), "+f"(c1), "+f"(c2), "+f"(c3)
        : "r"(a0), "r"(a1), "r"(a2), "r"(a3), "r"(b0), "r"(b1));
}
__device__ __forceinline__ uint64_t pack2(float lo, float hi) {
    uint64_t r; asm("mov.b64 %0,{%1,%2};" : "=l"(r) : "f"(lo), "f"(hi)); return r;
}
__device__ __forceinline__ void unpack2(uint64_t v, float& a, float& b) {
    asm("mov.b64 {%0,%1},%2;" : "=f"(a), "=f"(b) : "l"(v));
}
__device__ __forceinline__ uint64_t fmul2(uint64_t a, uint64_t b) {
    uint64_t d; asm("mul.rn.f32x2 %0,%1,%2;" : "=l"(d) : "l"(a), "l"(b)); return d;
}
__device__ __forceinline__ float rsqrt_a(float x){ float r; asm("rsqrt.approx.f32 %0,%1;" : "=f"(r) : "f"(x)); return r; }
__device__ __forceinline__ float sqrt_a (float x){ float r; asm("sqrt.approx.f32 %0,%1;"  : "=f"(r) : "f"(x)); return r; }
__device__ __forceinline__ float ex2_a  (float x){ float r; asm("ex2.approx.f32 %0,%1;"   : "=f"(r) : "f"(x)); return r; }
__device__ __forceinline__ float rcp_a  (float x){ float r; asm("rcp.approx.f32 %0,%1;"   : "=f"(r) : "f"(x)); return r; }

__global__ void __launch_bounds__(NWARPS * 32, 3)
engram_kernel(const float* __restrict__ emb,
              const float* __restrict__ hid,
              const float* __restrict__ Wv,
              const float* __restrict__ bv,
              const float* __restrict__ Wk,
              const float* __restrict__ bk,
              const float* __restrict__ g1,
              const float* __restrict__ g2,
              float* __restrict__ out,
              int ntiles)
{
    extern __shared__ char smem_raw[];
    Smem& s = *reinterpret_cast<Smem*>(smem_raw);

    const int tid  = threadIdx.x;
    const int lane = tid & 31;
    const int warp = tid >> 5;
    const int gr   = lane >> 2;   // fragment row group (token rows gr, gr+8)
    const int cq   = lane & 3;    // thread-in-group (col pairs 2cq, 2cq+1)

    // ---- one-time setup: B = [Wv; Wk0..3] as tf32, [d][n] stride 168 ----
    for (int i = tid; i < 32 * 160; i += blockDim.x) {
        int d = i / 160, n = i % 160;
        float w = (n < 32) ? Wv[n * 32 + d] : Wk[(size_t)(n - 32) * 32 + d];
        s.Bsm[d][n] = __uint_as_float(tf32_rna(w));
    }
    for (int i = tid; i < 160; i += blockDim.x)
        s.bias[i] = (i < 32) ? bv[i] : bk[i - 32];
    for (int i = tid; i < 128; i += blockDim.x)
        s.g12p[i / 32][i % 32] = g1[i] * g2[i];
    __syncthreads();

    const float EPSF  = 1.1920929e-07f;
    const float INV32 = 0.03125f;
    const float ISQ32 = 0.17677669529663687f;   // 1/sqrt(32)
    const float LOG2E = 1.4426950408889634f;

    float* qt = s.qT[warp];
    float* vt = s.valT[warp];
    const uint32_t qt_u = smem_u32(qt);
    const uint32_t vt_u = smem_u32(vt);

    for (int tile = blockIdx.x * NWARPS + warp; tile < ntiles;
         tile += gridDim.x * NWARPS) {

        const int base = tile * TOKPT;

        // ---- group 0: emb tile -> A-stage (valT region, stride 36) ----
        {
            const char* src = (const char*)(emb + (size_t)base * 32);
#pragma unroll
            for (int j = 0; j < 4; ++j) {
                int id = j * 32 + lane;               // 16B chunk id 0..127
                int t = id >> 3, ch = id & 7;
                cp_async16(vt_u + t * 144 + ch * 16, src + id * 16);
            }
            CP_COMMIT();
        }
        // ---- group 1: q tile -> qT rows [t][128], stride 132 ----
        {
            const char* src = (const char*)(hid + (size_t)base * 128);
#pragma unroll
            for (int t = 0; t < TOKPT; ++t)
                cp_async16(qt_u + t * 528 + lane * 16, src + t * 512 + lane * 16);
            CP_COMMIT();
        }
        CP_WAIT1();      // A landed
        __syncwarp();

        // ---- build A fragments (tf32), conflict-free: banks 4*gr + cq ----
        uint32_t A0[4], A1[4], A2[4], A3[4];
#pragma unroll
        for (int kf = 0; kf < 4; ++kf) {
            const float* Ar = vt + gr * 36 + 8 * kf + cq;
            A0[kf] = tf32_rna(Ar[0]);
            A2[kf] = tf32_rna(Ar[4]);
            const float* Ar8 = Ar + 8 * 36;
            A1[kf] = tf32_rna(Ar8[0]);
            A3[kf] = tf32_rna(Ar8[4]);
        }
        __syncwarp();    // A-stage fully read; valT region free for value writes

        // ---- value n-tiles 0..3 (no q dependency) ----
#pragma unroll
        for (int nt = 0; nt < NTILES_VAL; ++nt) {
            const int n0 = nt * 8;
            float2 bp = *reinterpret_cast<const float2*>(&s.bias[n0 + 2 * cq]);
            float c0 = bp.x, c1 = bp.y, c2 = bp.x, c3 = bp.y;
#pragma unroll
            for (int kf = 0; kf < 4; ++kf) {
                const float* Br = &s.Bsm[kf * 8 + cq][n0 + gr];
                uint32_t b0 = __float_as_uint(Br[0]);
                uint32_t b1 = __float_as_uint(Br[4 * 168]);
                mma_tf32(c0, c1, c2, c3, A0[kf], A1[kf], A2[kf], A3[kf], b0, b1);
            }
            *reinterpret_cast<float2*>(vt + gr * 36 + n0 + 2 * cq)       = make_float2(c0, c1);
            *reinterpret_cast<float2*>(vt + (gr + 8) * 36 + n0 + 2 * cq) = make_float2(c2, c3);
        }

        CP_WAIT0();      // q landed
        __syncwarp();

        // ---- key n-tiles, per head: mma + in-fragment gating partials ----
#pragma unroll
        for (int h = 0; h < 4; ++h) {
            float kssA = 0.f, kssB = 0.f, qssA = 0.f, qssB = 0.f;
            float pdA = 0.f, pdB = 0.f;
#pragma unroll
            for (int kg = 0; kg < 4; ++kg) {
                const int n0 = 32 + h * 32 + kg * 8;     // global n
                float2 bp = *reinterpret_cast<const float2*>(&s.bias[n0 + 2 * cq]);
                float c0 = bp.x, c1 = bp.y, c2 = bp.x, c3 = bp.y;
#pragma unroll
                for (int kf = 0; kf < 4; ++kf) {
                    const float* Br = &s.Bsm[kf * 8 + cq][n0 + gr];
                    uint32_t b0 = __float_as_uint(Br[0]);
                    uint32_t b1 = __float_as_uint(Br[4 * 168]);
                    mma_tf32(c0, c1, c2, c3, A0[kf], A1[kf], A2[kf], A3[kf], b0, b1);
                }
                const int kcol = kg * 8 + 2 * cq;        // k within head
                float2 g  = *reinterpret_cast<const float2*>(&s.g12p[h][kcol]);
                float2 qA = *reinterpret_cast<const float2*>(
                    qt + gr * 132 + h * 32 + kcol);
                float2 qB = *reinterpret_cast<const float2*>(
                    qt + (gr + 8) * 132 + h * 32 + kcol);

                kssA = fmaf(c0, c0, kssA); kssA = fmaf(c1, c1, kssA);
                kssB = fmaf(c2, c2, kssB); kssB = fmaf(c3, c3, kssB);
                qssA = fmaf(qA.x, qA.x, qssA); qssA = fmaf(qA.y, qA.y, qssA);
                qssB = fmaf(qB.x, qB.x, qssB); qssB = fmaf(qB.y, qB.y, qssB);
                pdA  = fmaf(c0, qA.x * g.x, pdA); pdA = fmaf(c1, qA.y * g.y, pdA);
                pdB  = fmaf(c2, qB.x * g.x, pdB); pdB = fmaf(c3, qB.y * g.y, pdB);
            }
            // reduce across the 4-lane quad (same token rows, disjoint k)
#pragma unroll
            for (int m = 1; m <= 2; m <<= 1) {
                kssA += __shfl_xor_sync(0xffffffffu, kssA, m);
                kssB += __shfl_xor_sync(0xffffffffu, kssB, m);
                qssA += __shfl_xor_sync(0xffffffffu, qssA, m);
                qssB += __shfl_xor_sync(0xffffffffu, qssB, m);
                pdA  += __shfl_xor_sync(0xffffffffu, pdA,  m);
                pdB  += __shfl_xor_sync(0xffffffffu, pdB,  m);
            }
            if (cq == 0) {
                s.sums[warp][h * 16 + gr]     = make_float4(kssA, qssA, pdA, 0.f);
                s.sums[warp][h * 16 + gr + 8] = make_float4(kssB, qssB, pdB, 0.f);
            }
        }
        __syncwarp();

        // ---- phase B: 64 gates at full lane efficiency ----
#pragma unroll
        for (int r = 0; r < 2; ++r) {
            int idx = r * 32 + lane;                // idx = h*16 + t
            float4 sv = s.sums[warp][idx];
            float rk = rsqrt_a(fmaf(sv.x, INV32, EPSF));
            float rq = rsqrt_a(fmaf(sv.y, INV32, EPSF));
            float gp = sv.z * rk * rq * ISQ32;
            float a  = fmaxf(fabsf(gp), 1e-6f);
            float sr = copysignf(sqrt_a(a), gp);
            float ex = ex2_a(-sr * LOG2E);
            s.gate[warp][idx] = rcp_a(1.f + ex);
        }
        __syncwarp();

        // ---- output: out[tok][h][k] = gate * value, lane = k ----
        float* outp = out + (size_t)base * 128;
#pragma unroll
        for (int p = 0; p < 8; ++p) {
            float v0 = vt[(2 * p) * 36 + lane];
            float v1 = vt[(2 * p + 1) * 36 + lane];
            uint64_t v2 = pack2(v0, v1);
#pragma unroll
            for (int h = 0; h < 4; ++h) {
                uint64_t g2v = *reinterpret_cast<const uint64_t*>(
                    &s.gate[warp][h * 16 + 2 * p]);
                uint64_t ov = fmul2(g2v, v2);
                float o0, o1; unpack2(ov, o0, o1);
                outp[(2 * p) * 128 + h * 32 + lane]     = o0;
                outp[(2 * p + 1) * 128 + h * 32 + lane] = o1;
            }
        }
        __syncwarp();   // protect valT/qT/gate before next tile's cp.async
    }
}

extern "C" void kernel_launch(void* const* d_in, const int* in_sizes, int n_in,
                              void* d_out, int out_size)
{
    const float* emb = (const float*)d_in[0];
    const float* hid = (const float*)d_in[1];
    const float* Wv  = (const float*)d_in[2];
    const float* bv  = (const float*)d_in[3];
    const float* Wk  = (const float*)d_in[4];
    const float* bk  = (const float*)d_in[5];
    const float* g1  = (const float*)d_in[6];
    const float* g2  = (const float*)d_in[7];

    int ntok   = in_sizes[0] / 32;     // B*S
    int ntiles = ntok / TOKPT;         // 16384 for this shape

    size_t smem = sizeof(Smem);
    cudaFuncSetAttribute(engram_kernel,
                         cudaFuncAttributeMaxDynamicSharedMemorySize, (int)smem);

    int blocks = 2048;                 // 8192 warps -> 2 tiles per warp
    engram_kernel<<<blocks, NWARPS * 32, smem>>>(
        emb, hid, Wv, bv, Wk, bk, g1, g2, (float*)d_out, ntiles);
}

// round 14
// speedup vs baseline: 1.1447x; 1.0129x over previous
#include <cuda_runtime.h>
#include <cstdint>

#define NWARPS  4
#define TOKPT   16

// ---- invariant operands, pre-packed in fragment order by prep_kernel ----
__device__ float2 d_Bfrag[20][4][32];   // [ntile][kf][lane]: (B[8kf+cq][n0+gr], B[8kf+cq+4][n0+gr])
__device__ float2 d_biasfrag[20][4];    // [ntile][cq]: bias cols (n0+2cq, n0+2cq+1)
__device__ float2 d_gfrag[4][4][4];     // [h][kg][cq]: g1*g2 at (kg*8+2cq, +1)

struct __align__(16) Smem {
    float qT[NWARPS][16 * 132];     // 33792 B  q rows [t][128], stride 132
    float scratch[NWARPS][16 * 36]; //  9216 B  A-stage / sums(float4) / value-transpose
    float gate[NWARPS][64];         //  1024 B
};                                  // 44032 B -> 4-5 CTAs/SM

__global__ void prep_kernel(const float* __restrict__ Wv, const float* __restrict__ bv,
                            const float* __restrict__ Wk, const float* __restrict__ bk,
                            const float* __restrict__ g1, const float* __restrict__ g2)
{
    int i = threadIdx.x;                       // 256 threads
    for (int e = i; e < 20 * 4 * 32; e += 256) {
        int nt = e >> 7, kf = (e >> 5) & 3, lane = e & 31;
        int gr = lane >> 2, cq = lane & 3;
        const float* row = (nt < 4) ? (Wv + (nt * 8 + gr) * 32)
                                    : (Wk + (size_t)((nt - 4) * 8 + gr) * 32);
        d_Bfrag[nt][kf][lane] = make_float2(row[8 * kf + cq], row[8 * kf + cq + 4]);
    }
    for (int e = i; e < 80; e += 256) {
        int nt = e >> 2, cq = e & 3;
        float b0, b1;
        if (nt < 4) { b0 = bv[nt * 8 + 2 * cq]; b1 = bv[nt * 8 + 2 * cq + 1]; }
        else { int k0 = (nt - 4) * 8; b0 = bk[k0 + 2 * cq]; b1 = bk[k0 + 2 * cq + 1]; }
        d_biasfrag[nt][cq] = make_float2(b0, b1);
    }
    for (int e = i; e < 64; e += 256) {
        int h = e >> 4, kg = (e >> 2) & 3, cq = e & 3;
        int k = h * 32 + kg * 8 + 2 * cq;
        d_gfrag[h][kg][cq] = make_float2(g1[k] * g2[k], g1[k + 1] * g2[k + 1]);
    }
}

__device__ __forceinline__ uint32_t smem_u32(const void* p) {
    uint32_t a; asm("{.reg .u64 t; cvta.to.shared.u64 t, %1; cvt.u32.u64 %0, t;}" : "=r"(a) : "l"(p));
    return a;
}
__device__ __forceinline__ void cp_async16(uint32_t dst, const void* src) {
    asm volatile("cp.async.cg.shared.global [%0], [%1], 16;" :: "r"(dst), "l"(src) : "memory");
}
#define CP_COMMIT() asm volatile("cp.async.commit_group;" ::: "memory")
#define CP_WAIT1()  asm volatile("cp.async.wait_group 1;" ::: "memory")
#define CP_WAIT0()  asm volatile("cp.async.wait_group 0;" ::: "memory")

__device__ __forceinline__ uint32_t tf32_rna(float x) {
    uint32_t r; asm("cvt.rna.tf32.f32 %0, %1;" : "=r"(r) : "f"(x)); return r;
}
__device__ __forceinline__ void mma_tf32(float& c0, float& c1, float& c2, float& c3,
                                         uint32_t a0, uint32_t a1, uint32_t a2, uint32_t a3,
                                         uint32_t b0, uint32_t b1) {
    asm volatile(
        "mma.sync.aligned.m16n8k8.row.col.f32.tf32.tf32.f32 "
        "{%0,%1,%2,%3}, {%4,%5,%6,%7}, {%8,%9}, {%0,%1,%2,%3};"
        : "+f"(c0), "+f"(c1), "+f"(c2), "+f"(c3)
        : "r"(a0), "r"(a1), "r"(a2), "r"(a3), "r"(b0), "r"(b1));
}
__device__ __forceinline__ uint64_t pack2(float lo, float hi) {
    uint64_t r; asm("mov.b64 %0,{%1,%2};" : "=l"(r) : "f"(lo), "f"(hi)); return r;
}
__device__ __forceinline__ void unpack2(uint64_t v, float& a, float& b) {
    asm("mov.b64 {%0,%1},%2;" : "=f"(a), "=f"(b) : "l"(v));
}
__device__ __forceinline__ uint64_t fmul2(uint64_t a, uint64_t b) {
    uint64_t d; asm("mul.rn.f32x2 %0,%1,%2;" : "=l"(d) : "l"(a), "l"(b)); return d;
}
__device__ __forceinline__ float rsqrt_a(float x){ float r; asm("rsqrt.approx.f32 %0,%1;" : "=f"(r) : "f"(x)); return r; }
__device__ __forceinline__ float sqrt_a (float x){ float r; asm("sqrt.approx.f32 %0,%1;"  : "=f"(r) : "f"(x)); return r; }
__device__ __forceinline__ float ex2_a  (float x){ float r; asm("ex2.approx.f32 %0,%1;"   : "=f"(r) : "f"(x)); return r; }
__device__ __forceinline__ float rcp_a  (float x){ float r; asm("rcp.approx.f32 %0,%1;"   : "=f"(r) : "f"(x)); return r; }

__global__ void __launch_bounds__(NWARPS * 32, 4)
engram_kernel(const float* __restrict__ emb,
              const float* __restrict__ hid,
              float* __restrict__ out,
              int ntiles)
{
    extern __shared__ char smem_raw[];
    Smem& s = *reinterpret_cast<Smem*>(smem_raw);

    const int tid  = threadIdx.x;
    const int lane = tid & 31;
    const int warp = tid >> 5;
    const int gr   = lane >> 2;   // fragment row group
    const int cq   = lane & 3;    // thread-in-group

    const float EPSF  = 1.1920929e-07f;
    const float INV32 = 0.03125f;
    const float ISQ32 = 0.17677669529663687f;   // 1/sqrt(32)
    const float LOG2E = 1.4426950408889634f;

    float* qt = s.qT[warp];
    float* sc = s.scratch[warp];
    float* gt = s.gate[warp];
    const uint32_t qt_u = smem_u32(qt);
    const uint32_t sc_u = smem_u32(sc);

    for (int tile = blockIdx.x * NWARPS + warp; tile < ntiles;
         tile += gridDim.x * NWARPS) {

        const int base = tile * TOKPT;

        // ---- group 0: emb -> scratch (A-stage, stride 36) ----
        {
            const char* src = (const char*)(emb + (size_t)base * 32);
#pragma unroll
            for (int j = 0; j < 4; ++j) {
                int id = j * 32 + lane;               // 16B chunk 0..127
                int t = id >> 3, ch = id & 7;
                cp_async16(sc_u + t * 144 + ch * 16, src + id * 16);
            }
            CP_COMMIT();
        }
        // ---- group 1: q -> qT rows [t][128], stride 132 ----
        {
            const char* src = (const char*)(hid + (size_t)base * 128);
#pragma unroll
            for (int t = 0; t < TOKPT; ++t)
                cp_async16(qt_u + t * 528 + lane * 16, src + t * 512 + lane * 16);
            CP_COMMIT();
        }
        CP_WAIT1();
        __syncwarp();

        // ---- A fragments (tf32) from scratch ----
        uint32_t A0[4], A1[4], A2[4], A3[4];
#pragma unroll
        for (int kf = 0; kf < 4; ++kf) {
            const float* Ar = sc + gr * 36 + 8 * kf + cq;
            A0[kf] = tf32_rna(Ar[0]);
            A2[kf] = tf32_rna(Ar[4]);
            const float* Ar8 = Ar + 8 * 36;
            A1[kf] = tf32_rna(Ar8[0]);
            A3[kf] = tf32_rna(Ar8[4]);
        }
        __syncwarp();    // A-stage read; scratch free

        // ---- value n-tiles: C kept in registers ----
        float vc[4][4];
#pragma unroll
        for (int nt = 0; nt < 4; ++nt) {
            float2 bp = d_biasfrag[nt][cq];
            float c0 = bp.x, c1 = bp.y, c2 = bp.x, c3 = bp.y;
#pragma unroll
            for (int kf = 0; kf < 4; ++kf) {
                float2 Bf = d_Bfrag[nt][kf][lane];        // coalesced, L1-hot
                mma_tf32(c0, c1, c2, c3, A0[kf], A1[kf], A2[kf], A3[kf],
                         __float_as_uint(Bf.x), __float_as_uint(Bf.y));
            }
            vc[nt][0] = c0; vc[nt][1] = c1; vc[nt][2] = c2; vc[nt][3] = c3;
        }

        CP_WAIT0();      // q landed
        __syncwarp();

        // ---- key n-tiles per head: mma + gating partials ----
#pragma unroll
        for (int h = 0; h < 4; ++h) {
            float kssA = 0.f, kssB = 0.f, qssA = 0.f, qssB = 0.f;
            float pdA = 0.f, pdB = 0.f;
#pragma unroll
            for (int kg = 0; kg < 4; ++kg) {
                const int nt = 4 + h * 4 + kg;
                float2 bp = d_biasfrag[nt][cq];
                float c0 = bp.x, c1 = bp.y, c2 = bp.x, c3 = bp.y;
#pragma unroll
                for (int kf = 0; kf < 4; ++kf) {
                    float2 Bf = d_Bfrag[nt][kf][lane];
                    mma_tf32(c0, c1, c2, c3, A0[kf], A1[kf], A2[kf], A3[kf],
                             __float_as_uint(Bf.x), __float_as_uint(Bf.y));
                }
                const int kcol = kg * 8 + 2 * cq;
                float2 g  = d_gfrag[h][kg][cq];
                float2 qA = *reinterpret_cast<const float2*>(qt + gr * 132 + h * 32 + kcol);
                float2 qB = *reinterpret_cast<const float2*>(qt + (gr + 8) * 132 + h * 32 + kcol);

                kssA = fmaf(c0, c0, kssA); kssA = fmaf(c1, c1, kssA);
                kssB = fmaf(c2, c2, kssB); kssB = fmaf(c3, c3, kssB);
                qssA = fmaf(qA.x, qA.x, qssA); qssA = fmaf(qA.y, qA.y, qssA);
                qssB = fmaf(qB.x, qB.x, qssB); qssB = fmaf(qB.y, qB.y, qssB);
                pdA  = fmaf(c0, qA.x * g.x, pdA); pdA = fmaf(c1, qA.y * g.y, pdA);
                pdB  = fmaf(c2, qB.x * g.x, pdB); pdB = fmaf(c3, qB.y * g.y, pdB);
            }
#pragma unroll
            for (int m = 1; m <= 2; m <<= 1) {
                kssA += __shfl_xor_sync(0xffffffffu, kssA, m);
                kssB += __shfl_xor_sync(0xffffffffu, kssB, m);
                qssA += __shfl_xor_sync(0xffffffffu, qssA, m);
                qssB += __shfl_xor_sync(0xffffffffu, qssB, m);
                pdA  += __shfl_xor_sync(0xffffffffu, pdA,  m);
                pdB  += __shfl_xor_sync(0xffffffffu, pdB,  m);
            }
            if (cq == 0) {
                float4* sums = reinterpret_cast<float4*>(sc);
                sums[h * 16 + gr]     = make_float4(kssA, qssA, pdA, 0.f);
                sums[h * 16 + gr + 8] = make_float4(kssB, qssB, pdB, 0.f);
            }
        }
        __syncwarp();

        // ---- phase B: 64 gates ----
#pragma unroll
        for (int r = 0; r < 2; ++r) {
            int idx = r * 32 + lane;                // idx = h*16 + t
            float4 sv = reinterpret_cast<const float4*>(sc)[idx];
            float rk = rsqrt_a(fmaf(sv.x, INV32, EPSF));
            float rq = rsqrt_a(fmaf(sv.y, INV32, EPSF));
            float gp = sv.z * rk * rq * ISQ32;
            float a  = fmaxf(fabsf(gp), 1e-6f);
            float sr = copysignf(sqrt_a(a), gp);
            float ex = ex2_a(-sr * LOG2E);
            gt[idx] = rcp_a(1.f + ex);
        }
        __syncwarp();    // sums dead; scratch free for value transpose

        // ---- value transpose: regs -> scratch rows (stride 36) ----
#pragma unroll
        for (int nt = 0; nt < 4; ++nt) {
            *reinterpret_cast<float2*>(sc + gr * 36 + nt * 8 + 2 * cq) =
                make_float2(vc[nt][0], vc[nt][1]);
            *reinterpret_cast<float2*>(sc + (gr + 8) * 36 + nt * 8 + 2 * cq) =
                make_float2(vc[nt][2], vc[nt][3]);
        }
        __syncwarp();

        // ---- output: out[tok][h][k] = gate * value, lane = k ----
        float* outp = out + (size_t)base * 128;
#pragma unroll
        for (int p = 0; p < 8; ++p) {
            float v0 = sc[(2 * p) * 36 + lane];
            float v1 = sc[(2 * p + 1) * 36 + lane];
            uint64_t v2 = pack2(v0, v1);
#pragma unroll
            for (int h = 0; h < 4; ++h) {
                uint64_t g2v = *reinterpret_cast<const uint64_t*>(&gt[h * 16 + 2 * p]);
                uint64_t ov = fmul2(g2v, v2);
                float o0, o1; unpack2(ov, o0, o1);
                outp[(2 * p) * 128 + h * 32 + lane]     = o0;
                outp[(2 * p + 1) * 128 + h * 32 + lane] = o1;
            }
        }
        __syncwarp();   // protect qT/scratch/gate before next tile's cp.async
    }
}

extern "C" void kernel_launch(void* const* d_in, const int* in_sizes, int n_in,
                              void* d_out, int out_size)
{
    const float* emb = (const float*)d_in[0];
    const float* hid = (const float*)d_in[1];
    const float* Wv  = (const float*)d_in[2];
    const float* bv  = (const float*)d_in[3];
    const float* Wk  = (const float*)d_in[4];
    const float* bk  = (const float*)d_in[5];
    const float* g1  = (const float*)d_in[6];
    const float* g2  = (const float*)d_in[7];

    int ntok   = in_sizes[0] / 32;     // B*S
    int ntiles = ntok / TOKPT;         // 16384 for this shape

    prep_kernel<<<1, 256>>>(Wv, bv, Wk, bk, g1, g2);

    size_t smem = sizeof(Smem);
    cudaFuncSetAttribute(engram_kernel,
                         cudaFuncAttributeMaxDynamicSharedMemorySize, (int)smem);

    int blocks = 2048;                 // 8192 warps -> 2 tiles per warp
    engram_kernel<<<blocks, NWARPS * 32, smem>>>(emb, hid, (float*)d_out, ntiles);
}

// round 15
// speedup vs baseline: 1.4114x; 1.2330x over previous
#include <cuda_runtime.h>
#include <cstdint>

#define NWARPS  4
#define TOKPT   16

// ---- invariant operands, pre-packed in fragment order by prep_kernel ----
__device__ float2 d_Bfrag[20][4][32];   // [ntile][kf][lane]: (B[8kf+cq][n0+gr], B[8kf+cq+4][n0+gr])
__device__ float2 d_biasfrag[20][4];    // [ntile][cq]: bias cols (n0+2cq, n0+2cq+1)
__device__ float2 d_gfrag[4][4][4];     // [h][kg][cq]: g1*g2 at (kg*8+2cq, +1)

struct __align__(16) Smem {
    float qT[NWARPS][16 * 132];     // 33792 B  q rows [t][128], stride 132
    float scratch[NWARPS][16 * 36]; //  9216 B  A-stage / sums(float4) / value-transpose
    float gate[NWARPS][64];         //  1024 B
};                                  // 44032 B -> 4 CTAs/SM

__global__ void prep_kernel(const float* __restrict__ Wv, const float* __restrict__ bv,
                            const float* __restrict__ Wk, const float* __restrict__ bk,
                            const float* __restrict__ g1, const float* __restrict__ g2)
{
    const int i = blockIdx.x * blockDim.x + threadIdx.x;   // 20 x 128 = 2560 threads
    // B fragments: exactly 2560 elements, one per thread
    {
        int e = i;
        int nt = e >> 7, kf = (e >> 5) & 3, lane = e & 31;
        int gr = lane >> 2, cq = lane & 3;
        const float* row = (nt < 4) ? (Wv + (nt * 8 + gr) * 32)
                                    : (Wk + (size_t)((nt - 4) * 8 + gr) * 32);
        d_Bfrag[nt][kf][lane] = make_float2(row[8 * kf + cq], row[8 * kf + cq + 4]);
    }
    if (i < 80) {
        int nt = i >> 2, cq = i & 3;
        float b0, b1;
        if (nt < 4) { b0 = bv[nt * 8 + 2 * cq]; b1 = bv[nt * 8 + 2 * cq + 1]; }
        else { int k0 = (nt - 4) * 8; b0 = bk[k0 + 2 * cq]; b1 = bk[k0 + 2 * cq + 1]; }
        d_biasfrag[nt][cq] = make_float2(b0, b1);
    }
    if (i >= 128 && i < 192) {
        int e = i - 128;
        int h = e >> 4, kg = (e >> 2) & 3, cq = e & 3;
        int k = h * 32 + kg * 8 + 2 * cq;
        d_gfrag[h][kg][cq] = make_float2(g1[k] * g2[k], g1[k + 1] * g2[k + 1]);
    }
}

__device__ __forceinline__ uint32_t smem_u32(const void* p) {
    uint32_t a; asm("{.reg .u64 t; cvta.to.shared.u64 t, %1; cvt.u32.u64 %0, t;}" : "=r"(a) : "l"(p));
    return a;
}
__device__ __forceinline__ void cp_async16(uint32_t dst, const void* src) {
    asm volatile("cp.async.cg.shared.global [%0], [%1], 16;" :: "r"(dst), "l"(src) : "memory");
}
#define CP_COMMIT() asm volatile("cp.async.commit_group;" ::: "memory")
#define CP_WAIT1()  asm volatile("cp.async.wait_group 1;" ::: "memory")
#define CP_WAIT0()  asm volatile("cp.async.wait_group 0;" ::: "memory")

__device__ __forceinline__ uint32_t tf32_rna(float x) {
    uint32_t r; asm("cvt.rna.tf32.f32 %0, %1;" : "=r"(r) : "f"(x)); return r;
}
__device__ __forceinline__ void mma_tf32(float& c0, float& c1, float& c2, float& c3,
                                         uint32_t a0, uint32_t a1, uint32_t a2, uint32_t a3,
                                         uint32_t b0, uint32_t b1) {
    asm volatile(
        "mma.sync.aligned.m16n8k8.row.col.f32.tf32.tf32.f32 "
        "{%0,%1,%2,%3}, {%4,%5,%6,%7}, {%8,%9}, {%0,%1,%2,%3};"
        : "+f"(c0), "+f"(c1), "+f"(c2), "+f"(c3)
        : "r"(a0), "r"(a1), "r"(a2), "r"(a3), "r"(b0), "r"(b1));
}
__device__ __forceinline__ uint64_t pack2(float lo, float hi) {
    uint64_t r; asm("mov.b64 %0,{%1,%2};" : "=l"(r) : "f"(lo), "f"(hi)); return r;
}
__device__ __forceinline__ void unpack2(uint64_t v, float& a, float& b) {
    asm("mov.b64 {%0,%1},%2;" : "=f"(a), "=f"(b) : "l"(v));
}
__device__ __forceinline__ uint64_t fmul2(uint64_t a, uint64_t b) {
    uint64_t d; asm("mul.rn.f32x2 %0,%1,%2;" : "=l"(d) : "l"(a), "l"(b)); return d;
}
__device__ __forceinline__ float rsqrt_a(float x){ float r; asm("rsqrt.approx.f32 %0,%1;" : "=f"(r) : "f"(x)); return r; }
__device__ __forceinline__ float sqrt_a (float x){ float r; asm("sqrt.approx.f32 %0,%1;"  : "=f"(r) : "f"(x)); return r; }
__device__ __forceinline__ float ex2_a  (float x){ float r; asm("ex2.approx.f32 %0,%1;"   : "=f"(r) : "f"(x)); return r; }
__device__ __forceinline__ float rcp_a  (float x){ float r; asm("rcp.approx.f32 %0,%1;"   : "=f"(r) : "f"(x)); return r; }

__global__ void __launch_bounds__(NWARPS * 32, 4)
engram_kernel(const float* __restrict__ emb,
              const float* __restrict__ hid,
              float* __restrict__ out,
              int ntiles)
{
    extern __shared__ char smem_raw[];
    Smem& s = *reinterpret_cast<Smem*>(smem_raw);

    const int tid  = threadIdx.x;
    const int lane = tid & 31;
    const int warp = tid >> 5;
    const int gr   = lane >> 2;   // fragment row group
    const int cq   = lane & 3;    // thread-in-group

    const float EPSF  = 1.1920929e-07f;
    const float INV32 = 0.03125f;
    const float ISQ32 = 0.17677669529663687f;   // 1/sqrt(32)
    const float LOG2E = 1.4426950408889634f;

    float* qt = s.qT[warp];
    float* sc = s.scratch[warp];
    float* gt = s.gate[warp];
    const uint32_t qt_u = smem_u32(qt);
    const uint32_t sc_u = smem_u32(sc);

    for (int tile = blockIdx.x * NWARPS + warp; tile < ntiles;
         tile += gridDim.x * NWARPS) {

        const int base = tile * TOKPT;

        // ---- group 0: emb -> scratch (A-stage, stride 36) ----
        {
            const char* src = (const char*)(emb + (size_t)base * 32);
#pragma unroll
            for (int j = 0; j < 4; ++j) {
                int id = j * 32 + lane;               // 16B chunk 0..127
                int t = id >> 3, ch = id & 7;
                cp_async16(sc_u + t * 144 + ch * 16, src + id * 16);
            }
            CP_COMMIT();
        }
        // ---- group 1: q -> qT rows [t][128], stride 132 ----
        {
            const char* src = (const char*)(hid + (size_t)base * 128);
#pragma unroll
            for (int t = 0; t < TOKPT; ++t)
                cp_async16(qt_u + t * 528 + lane * 16, src + t * 512 + lane * 16);
            CP_COMMIT();
        }
        CP_WAIT1();
        __syncwarp();

        // ---- A fragments (tf32) from scratch ----
        uint32_t A0[4], A1[4], A2[4], A3[4];
#pragma unroll
        for (int kf = 0; kf < 4; ++kf) {
            const float* Ar = sc + gr * 36 + 8 * kf + cq;
            A0[kf] = tf32_rna(Ar[0]);
            A2[kf] = tf32_rna(Ar[4]);
            const float* Ar8 = Ar + 8 * 36;
            A1[kf] = tf32_rna(Ar8[0]);
            A3[kf] = tf32_rna(Ar8[4]);
        }
        __syncwarp();    // A-stage read; scratch free

        // ---- value n-tiles: C kept in registers ----
        float vc[4][4];
#pragma unroll
        for (int nt = 0; nt < 4; ++nt) {
            float2 bp = d_biasfrag[nt][cq];
            float c0 = bp.x, c1 = bp.y, c2 = bp.x, c3 = bp.y;
#pragma unroll
            for (int kf = 0; kf < 4; ++kf) {
                float2 Bf = d_Bfrag[nt][kf][lane];        // coalesced, L1-hot
                mma_tf32(c0, c1, c2, c3, A0[kf], A1[kf], A2[kf], A3[kf],
                         __float_as_uint(Bf.x), __float_as_uint(Bf.y));
            }
            vc[nt][0] = c0; vc[nt][1] = c1; vc[nt][2] = c2; vc[nt][3] = c3;
        }

        CP_WAIT0();      // q landed
        __syncwarp();

        // ---- key n-tiles per head: mma + gating partials ----
#pragma unroll
        for (int h = 0; h < 4; ++h) {
            float kssA = 0.f, kssB = 0.f, qssA = 0.f, qssB = 0.f;
            float pdA = 0.f, pdB = 0.f;
#pragma unroll
            for (int kg = 0; kg < 4; ++kg) {
                const int nt = 4 + h * 4 + kg;
                float2 bp = d_biasfrag[nt][cq];
                float c0 = bp.x, c1 = bp.y, c2 = bp.x, c3 = bp.y;
#pragma unroll
                for (int kf = 0; kf < 4; ++kf) {
                    float2 Bf = d_Bfrag[nt][kf][lane];
                    mma_tf32(c0, c1, c2, c3, A0[kf], A1[kf], A2[kf], A3[kf],
                             __float_as_uint(Bf.x), __float_as_uint(Bf.y));
                }
                const int kcol = kg * 8 + 2 * cq;
                float2 g  = d_gfrag[h][kg][cq];
                float2 qA = *reinterpret_cast<const float2*>(qt + gr * 132 + h * 32 + kcol);
                float2 qB = *reinterpret_cast<const float2*>(qt + (gr + 8) * 132 + h * 32 + kcol);

                kssA = fmaf(c0, c0, kssA); kssA = fmaf(c1, c1, kssA);
                kssB = fmaf(c2, c2, kssB); kssB = fmaf(c3, c3, kssB);
                qssA = fmaf(qA.x, qA.x, qssA); qssA = fmaf(qA.y, qA.y, qssA);
                qssB = fmaf(qB.x, qB.x, qssB); qssB = fmaf(qB.y, qB.y, qssB);
                pdA  = fmaf(c0, qA.x * g.x, pdA); pdA = fmaf(c1, qA.y * g.y, pdA);
                pdB  = fmaf(c2, qB.x * g.x, pdB); pdB = fmaf(c3, qB.y * g.y, pdB);
            }
#pragma unroll
            for (int m = 1; m <= 2; m <<= 1) {
                kssA += __shfl_xor_sync(0xffffffffu, kssA, m);
                kssB += __shfl_xor_sync(0xffffffffu, kssB, m);
                qssA += __shfl_xor_sync(0xffffffffu, qssA, m);
                qssB += __shfl_xor_sync(0xffffffffu, qssB, m);
                pdA  += __shfl_xor_sync(0xffffffffu, pdA,  m);
                pdB  += __shfl_xor_sync(0xffffffffu, pdB,  m);
            }
            if (cq == 0) {
                float4* sums = reinterpret_cast<float4*>(sc);
                sums[h * 16 + gr]     = make_float4(kssA, qssA, pdA, 0.f);
                sums[h * 16 + gr + 8] = make_float4(kssB, qssB, pdB, 0.f);
            }
        }
        __syncwarp();

        // ---- phase B: 64 gates ----
#pragma unroll
        for (int r = 0; r < 2; ++r) {
            int idx = r * 32 + lane;                // idx = h*16 + t
            float4 sv = reinterpret_cast<const float4*>(sc)[idx];
            float rk = rsqrt_a(fmaf(sv.x, INV32, EPSF));
            float rq = rsqrt_a(fmaf(sv.y, INV32, EPSF));
            float gp = sv.z * rk * rq * ISQ32;
            float a  = fmaxf(fabsf(gp), 1e-6f);
            float sr = copysignf(sqrt_a(a), gp);
            float ex = ex2_a(-sr * LOG2E);
            gt[idx] = rcp_a(1.f + ex);
        }
        __syncwarp();    // sums dead; scratch free for value transpose

        // ---- value transpose: regs -> scratch rows (stride 36) ----
#pragma unroll
        for (int nt = 0; nt < 4; ++nt) {
            *reinterpret_cast<float2*>(sc + gr * 36 + nt * 8 + 2 * cq) =
                make_float2(vc[nt][0], vc[nt][1]);
            *reinterpret_cast<float2*>(sc + (gr + 8) * 36 + nt * 8 + 2 * cq) =
                make_float2(vc[nt][2], vc[nt][3]);
        }
        __syncwarp();

        // ---- output: out[tok][h][k] = gate * value, lane = k ----
        float* outp = out + (size_t)base * 128;
#pragma unroll
        for (int p = 0; p < 8; ++p) {
            float v0 = sc[(2 * p) * 36 + lane];
            float v1 = sc[(2 * p + 1) * 36 + lane];
            uint64_t v2 = pack2(v0, v1);
#pragma unroll
            for (int h = 0; h < 4; ++h) {
                uint64_t g2v = *reinterpret_cast<const uint64_t*>(&gt[h * 16 + 2 * p]);
                uint64_t ov = fmul2(g2v, v2);
                float o0, o1; unpack2(ov, o0, o1);
                outp[(2 * p) * 128 + h * 32 + lane]     = o0;
                outp[(2 * p + 1) * 128 + h * 32 + lane] = o1;
            }
        }
        __syncwarp();   // protect qT/scratch/gate before next tile's cp.async
    }
}

extern "C" void kernel_launch(void* const* d_in, const int* in_sizes, int n_in,
                              void* d_out, int out_size)
{
    const float* emb = (const float*)d_in[0];
    const float* hid = (const float*)d_in[1];
    const float* Wv  = (const float*)d_in[2];
    const float* bv  = (const float*)d_in[3];
    const float* Wk  = (const float*)d_in[4];
    const float* bk  = (const float*)d_in[5];
    const float* g1  = (const float*)d_in[6];
    const float* g2  = (const float*)d_in[7];

    int ntok   = in_sizes[0] / 32;     // B*S
    int ntiles = ntok / TOKPT;         // 16384 for this shape

    prep_kernel<<<20, 128>>>(Wv, bv, Wk, bk, g1, g2);   // one block per n-tile

    size_t smem = sizeof(Smem);
    cudaFuncSetAttribute(engram_kernel,
                         cudaFuncAttributeMaxDynamicSharedMemorySize, (int)smem);

    int blocks = 2048;                 // 8192 warps -> 2 tiles per warp
    engram_kernel<<<blocks, NWARPS * 32, smem>>>(emb, hid, (float*)d_out, ntiles);
}

// round 16
// speedup vs baseline: 1.6227x; 1.1497x over previous
#include <cuda_runtime.h>
#include <cstdint>

#define NWARPS  4
#define TOKPT   16

// ---- invariant operands, pre-packed in fragment order by prep_kernel ----
__device__ float2 d_Bfrag[20][4][32];   // [ntile][kf][lane]
__device__ float2 d_biasfrag[20][4];    // [ntile][cq]
__device__ float2 d_gfrag[4][4][4];     // [h][kg][cq]

struct __align__(16) Smem {
    float qT[NWARPS][16 * 132];     // 33792 B  q rows [t][128], stride 132
    float scratch[NWARPS][16 * 36]; //  9216 B  A-stage -> value rows (stride 36)
    float gate[NWARPS][64];         //  1024 B  [h*16 + t]
};                                  // 44032 B -> 5 CTAs/SM (regs permitting)

__global__ void prep_kernel(const float* __restrict__ Wv, const float* __restrict__ bv,
                            const float* __restrict__ Wk, const float* __restrict__ bk,
                            const float* __restrict__ g1, const float* __restrict__ g2)
{
    const int i = blockIdx.x * blockDim.x + threadIdx.x;   // 20 x 128
    {
        int e = i;
        int nt = e >> 7, kf = (e >> 5) & 3, lane = e & 31;
        int gr = lane >> 2, cq = lane & 3;
        const float* row = (nt < 4) ? (Wv + (nt * 8 + gr) * 32)
                                    : (Wk + (size_t)((nt - 4) * 8 + gr) * 32);
        d_Bfrag[nt][kf][lane] = make_float2(row[8 * kf + cq], row[8 * kf + cq + 4]);
    }
    if (i < 80) {
        int nt = i >> 2, cq = i & 3;
        float b0, b1;
        if (nt < 4) { b0 = bv[nt * 8 + 2 * cq]; b1 = bv[nt * 8 + 2 * cq + 1]; }
        else { int k0 = (nt - 4) * 8; b0 = bk[k0 + 2 * cq]; b1 = bk[k0 + 2 * cq + 1]; }
        d_biasfrag[nt][cq] = make_float2(b0, b1);
    }
    if (i >= 128 && i < 192) {
        int e = i - 128;
        int h = e >> 4, kg = (e >> 2) & 3, cq = e & 3;
        int k = h * 32 + kg * 8 + 2 * cq;
        d_gfrag[h][kg][cq] = make_float2(g1[k] * g2[k], g1[k + 1] * g2[k + 1]);
    }
}

__device__ __forceinline__ uint32_t smem_u32(const void* p) {
    uint32_t a; asm("{.reg .u64 t; cvta.to.shared.u64 t, %1; cvt.u32.u64 %0, t;}" : "=r"(a) : "l"(p));
    return a;
}
__device__ __forceinline__ void cp_async16(uint32_t dst, const void* src) {
    asm volatile("cp.async.cg.shared.global [%0], [%1], 16;" :: "r"(dst), "l"(src) : "memory");
}
#define CP_COMMIT() asm volatile("cp.async.commit_group;" ::: "memory")
#define CP_WAIT1()  asm volatile("cp.async.wait_group 1;" ::: "memory")
#define CP_WAIT0()  asm volatile("cp.async.wait_group 0;" ::: "memory")

__device__ __forceinline__ uint32_t tf32_rna(float x) {
    uint32_t r; asm("cvt.rna.tf32.f32 %0, %1;" : "=r"(r) : "f"(x)); return r;
}
__device__ __forceinline__ void mma_tf32(float& c0, float& c1, float& c2, float& c3,
                                         uint32_t a0, uint32_t a1, uint32_t a2, uint32_t a3,
                                         uint32_t b0, uint32_t b1) {
    asm volatile(
        "mma.sync.aligned.m16n8k8.row.col.f32.tf32.tf32.f32 "
        "{%0,%1,%2,%3}, {%4,%5,%6,%7}, {%8,%9}, {%0,%1,%2,%3};"
        : "+f"(c0), "+f"(c1), "+f"(c2), "+f"(c3)
        : "r"(a0), "r"(a1), "r"(a2), "r"(a3), "r"(b0), "r"(b1));
}
__device__ __forceinline__ uint64_t pack2(float lo, float hi) {
    uint64_t r; asm("mov.b64 %0,{%1,%2};" : "=l"(r) : "f"(lo), "f"(hi)); return r;
}
__device__ __forceinline__ void unpack2(uint64_t v, float& a, float& b) {
    asm("mov.b64 {%0,%1},%2;" : "=f"(a), "=f"(b) : "l"(v));
}
__device__ __forceinline__ uint64_t fmul2(uint64_t a, uint64_t b) {
    uint64_t d; asm("mul.rn.f32x2 %0,%1,%2;" : "=l"(d) : "l"(a), "l"(b)); return d;
}
__device__ __forceinline__ float rsqrt_a(float x){ float r; asm("rsqrt.approx.f32 %0,%1;" : "=f"(r) : "f"(x)); return r; }
__device__ __forceinline__ float sqrt_a (float x){ float r; asm("sqrt.approx.f32 %0,%1;"  : "=f"(r) : "f"(x)); return r; }
__device__ __forceinline__ float ex2_a  (float x){ float r; asm("ex2.approx.f32 %0,%1;"   : "=f"(r) : "f"(x)); return r; }
__device__ __forceinline__ float rcp_a  (float x){ float r; asm("rcp.approx.f32 %0,%1;"   : "=f"(r) : "f"(x)); return r; }

__global__ void __launch_bounds__(NWARPS * 32, 5)
engram_kernel(const float* __restrict__ emb,
              const float* __restrict__ hid,
              float* __restrict__ out,
              int ntiles)
{
    extern __shared__ char smem_raw[];
    Smem& s = *reinterpret_cast<Smem*>(smem_raw);

    const int tid  = threadIdx.x;
    const int lane = tid & 31;
    const int warp = tid >> 5;
    const int gr   = lane >> 2;   // fragment row group
    const int cq   = lane & 3;    // thread-in-group

    const float EPSF  = 1.1920929e-07f;
    const float INV32 = 0.03125f;
    const float ISQ32 = 0.17677669529663687f;   // 1/sqrt(32)
    const float LOG2E = 1.4426950408889634f;

    float* qt = s.qT[warp];
    float* sc = s.scratch[warp];
    float* gt = s.gate[warp];
    const uint32_t qt_u = smem_u32(qt);
    const uint32_t sc_u = smem_u32(sc);

    for (int tile = blockIdx.x * NWARPS + warp; tile < ntiles;
         tile += gridDim.x * NWARPS) {

        const int base = tile * TOKPT;

        // ---- group 0: emb -> scratch (A-stage, stride 36) ----
        {
            const char* src = (const char*)(emb + (size_t)base * 32);
#pragma unroll
            for (int j = 0; j < 4; ++j) {
                int id = j * 32 + lane;               // 16B chunk 0..127
                int t = id >> 3, ch = id & 7;
                cp_async16(sc_u + t * 144 + ch * 16, src + id * 16);
            }
            CP_COMMIT();
        }
        // ---- group 1: q -> qT rows [t][128], stride 132 ----
        {
            const char* src = (const char*)(hid + (size_t)base * 128);
#pragma unroll
            for (int t = 0; t < TOKPT; ++t)
                cp_async16(qt_u + t * 528 + lane * 16, src + t * 512 + lane * 16);
            CP_COMMIT();
        }
        CP_WAIT1();
        __syncwarp();

        // ---- A fragments (tf32) from scratch ----
        uint32_t A0[4], A1[4], A2[4], A3[4];
#pragma unroll
        for (int kf = 0; kf < 4; ++kf) {
            const float* Ar = sc + gr * 36 + 8 * kf + cq;
            A0[kf] = tf32_rna(Ar[0]);
            A2[kf] = tf32_rna(Ar[4]);
            const float* Ar8 = Ar + 8 * 36;
            A1[kf] = tf32_rna(Ar8[0]);
            A3[kf] = tf32_rna(Ar8[4]);
        }
        __syncwarp();    // all lanes done reading A-stage; scratch reusable

        // ---- value n-tiles: C frags written straight to scratch ----
#pragma unroll
        for (int nt = 0; nt < 4; ++nt) {
            float2 bp = d_biasfrag[nt][cq];
            float c0 = bp.x, c1 = bp.y, c2 = bp.x, c3 = bp.y;
#pragma unroll
            for (int kf = 0; kf < 4; ++kf) {
                float2 Bf = d_Bfrag[nt][kf][lane];        // coalesced, L1-hot
                mma_tf32(c0, c1, c2, c3, A0[kf], A1[kf], A2[kf], A3[kf],
                         __float_as_uint(Bf.x), __float_as_uint(Bf.y));
            }
            *reinterpret_cast<float2*>(sc + gr * 36 + nt * 8 + 2 * cq)       = make_float2(c0, c1);
            *reinterpret_cast<float2*>(sc + (gr + 8) * 36 + nt * 8 + 2 * cq) = make_float2(c2, c3);
        }

        CP_WAIT0();      // q landed (covered by value mma)
        __syncwarp();

        // ---- key n-tiles per head: mma + gating partials + inline gates ----
#pragma unroll
        for (int h = 0; h < 4; ++h) {
            float kssA = 0.f, kssB = 0.f, qssA = 0.f, qssB = 0.f;
            float pdA = 0.f, pdB = 0.f;
#pragma unroll
            for (int kg = 0; kg < 4; ++kg) {
                const int nt = 4 + h * 4 + kg;
                float2 bp = d_biasfrag[nt][cq];
                float c0 = bp.x, c1 = bp.y, c2 = bp.x, c3 = bp.y;
#pragma unroll
                for (int kf = 0; kf < 4; ++kf) {
                    float2 Bf = d_Bfrag[nt][kf][lane];
                    mma_tf32(c0, c1, c2, c3, A0[kf], A1[kf], A2[kf], A3[kf],
                             __float_as_uint(Bf.x), __float_as_uint(Bf.y));
                }
                const int kcol = kg * 8 + 2 * cq;
                float2 g  = d_gfrag[h][kg][cq];
                float2 qA = *reinterpret_cast<const float2*>(qt + gr * 132 + h * 32 + kcol);
                float2 qB = *reinterpret_cast<const float2*>(qt + (gr + 8) * 132 + h * 32 + kcol);

                kssA = fmaf(c0, c0, kssA); kssA = fmaf(c1, c1, kssA);
                kssB = fmaf(c2, c2, kssB); kssB = fmaf(c3, c3, kssB);
                qssA = fmaf(qA.x, qA.x, qssA); qssA = fmaf(qA.y, qA.y, qssA);
                qssB = fmaf(qB.x, qB.x, qssB); qssB = fmaf(qB.y, qB.y, qssB);
                pdA  = fmaf(c0, qA.x * g.x, pdA); pdA = fmaf(c1, qA.y * g.y, pdA);
                pdB  = fmaf(c2, qB.x * g.x, pdB); pdB = fmaf(c3, qB.y * g.y, pdB);
            }
            // quad butterfly: all 4 lanes end with full sums for tokens gr, gr+8
#pragma unroll
            for (int m = 1; m <= 2; m <<= 1) {
                kssA += __shfl_xor_sync(0xffffffffu, kssA, m);
                kssB += __shfl_xor_sync(0xffffffffu, kssB, m);
                qssA += __shfl_xor_sync(0xffffffffu, qssA, m);
                qssB += __shfl_xor_sync(0xffffffffu, qssB, m);
                pdA  += __shfl_xor_sync(0xffffffffu, pdA,  m);
                pdB  += __shfl_xor_sync(0xffffffffu, pdB,  m);
            }
            // inline gates: cq=0 -> token gr, cq=1 -> token gr+8
            {
                float ks = (cq & 1) ? kssB : kssA;
                float qs = (cq & 1) ? qssB : qssA;
                float pd = (cq & 1) ? pdB  : pdA;
                float rk = rsqrt_a(fmaf(ks, INV32, EPSF));
                float rq = rsqrt_a(fmaf(qs, INV32, EPSF));
                float gp = pd * rk * rq * ISQ32;
                float a  = fmaxf(fabsf(gp), 1e-6f);
                float sr = copysignf(sqrt_a(a), gp);
                float ex = ex2_a(-sr * LOG2E);
                float gv = rcp_a(1.f + ex);
                if (cq < 2) gt[h * 16 + gr + 8 * (cq & 1)] = gv;
            }
        }
        __syncwarp();    // gates + value rows visible warp-wide

        // ---- output: out[tok][h][k] = gate * value, lane = k ----
        float* outp = out + (size_t)base * 128;
#pragma unroll
        for (int p = 0; p < 8; ++p) {
            float v0 = sc[(2 * p) * 36 + lane];
            float v1 = sc[(2 * p + 1) * 36 + lane];
            uint64_t v2 = pack2(v0, v1);
#pragma unroll
            for (int h = 0; h < 4; ++h) {
                uint64_t g2v = *reinterpret_cast<const uint64_t*>(&gt[h * 16 + 2 * p]);
                uint64_t ov = fmul2(g2v, v2);
                float o0, o1; unpack2(ov, o0, o1);
                outp[(2 * p) * 128 + h * 32 + lane]     = o0;
                outp[(2 * p + 1) * 128 + h * 32 + lane] = o1;
            }
        }
        __syncwarp();   // protect qT/scratch/gate before next tile's cp.async
    }
}

extern "C" void kernel_launch(void* const* d_in, const int* in_sizes, int n_in,
                              void* d_out, int out_size)
{
    const float* emb = (const float*)d_in[0];
    const float* hid = (const float*)d_in[1];
    const float* Wv  = (const float*)d_in[2];
    const float* bv  = (const float*)d_in[3];
    const float* Wk  = (const float*)d_in[4];
    const float* bk  = (const float*)d_in[5];
    const float* g1  = (const float*)d_in[6];
    const float* g2  = (const float*)d_in[7];

    int ntok   = in_sizes[0] / 32;     // B*S
    int ntiles = ntok / TOKPT;         // 16384 for this shape

    prep_kernel<<<20, 128>>>(Wv, bv, Wk, bk, g1, g2);

    size_t smem = sizeof(Smem);
    cudaFuncSetAttribute(engram_kernel,
                         cudaFuncAttributeMaxDynamicSharedMemorySize, (int)smem);

    int blocks = 2048;
    engram_kernel<<<blocks, NWARPS * 32, smem>>>(emb, hid, (float*)d_out, ntiles);
}